// round 6
// baseline (speedup 1.0000x reference)
#include <cuda_runtime.h>
#include <math.h>

// Problem constants: b=2, nc=64, H=W=64
#define Bz 2
#define NC 64
#define Hh 64
#define Ww 64
#define Ls 4096          // H*W
#define KD 576           // nc * 3 * 3
#define EPSF 1e-7f
#define CQ   3           // k_corr candidate chunk per block
#define FCH  16          // k_softrec candidate chunk (fast path if cnt<=FCH)

// Scratch (worst-case cnt == Ls; actual data gives cnt ~ 12 per sample)
__device__ int   g_cnt[Bz];
__device__ int   g_list[Bz][Ls];
__device__ float g_K[Bz][Ls][KD];     // normalized bg patch rows (candidates only)
__device__ float g_corr[Bz][Ls][Ls];  // corr rows   (candidates only)

// ---------------------------------------------------------------------------
// K1: per-sample, ONE 1024-thread block. Phase A: mm[l] + block scan ->
// ordered candidate list. Phase B: build normalized kernel rows (16 at a time).
// ---------------------------------------------------------------------------
__global__ void k_scanbuild(const float* __restrict__ mask,
                            const float* __restrict__ bgin) {
    int b = blockIdx.x;
    const float* m = mask + b * Ls;
    int tid = threadIdx.x, lane = tid & 31, warp = tid >> 5;
    __shared__ int   wsum[32];
    __shared__ int   s_list[Ls];      // 16KB
    __shared__ int   s_cnt;
    __shared__ float s_norm[32];

    int ok[4]; int myc = 0;
    #pragma unroll
    for (int j = 0; j < 4; j++) {
        int l = tid * 4 + j;
        int y = l >> 6, x = l & 63;
        int o = 1;
        #pragma unroll
        for (int dy = -1; dy <= 1; dy++) {
            int yy = y + dy;
            if (yy < 0 || yy >= Hh) continue;
            #pragma unroll
            for (int dx = -1; dx <= 1; dx++) {
                int xx = x + dx;
                if (xx >= 0 && xx < Ww && m[yy * Ww + xx] != 0.0f) o = 0;
            }
        }
        ok[j] = o; myc += o;
    }
    int v = myc;
    #pragma unroll
    for (int off = 1; off < 32; off <<= 1) {
        int t = __shfl_up_sync(0xffffffffu, v, off);
        if (lane >= off) v += t;
    }
    if (lane == 31) wsum[warp] = v;
    __syncthreads();
    if (warp == 0) {
        int t = wsum[lane];
        #pragma unroll
        for (int off = 1; off < 32; off <<= 1) {
            int u = __shfl_up_sync(0xffffffffu, t, off);
            if (lane >= off) t += u;
        }
        wsum[lane] = t;
    }
    __syncthreads();
    int excl = (v - myc) + (warp > 0 ? wsum[warp - 1] : 0);
    #pragma unroll
    for (int j = 0; j < 4; j++)
        if (ok[j]) s_list[excl++] = tid * 4 + j;
    if (tid == 0) { s_cnt = wsum[31]; g_cnt[b] = wsum[31]; }
    __syncthreads();
    int cnt = s_cnt;
    for (int t = tid; t < cnt; t += 1024) g_list[b][t] = s_list[t];

    // ---- Phase B: build normalized kernels, 16 candidates at a time ----
    int grp = tid >> 6;     // 0..15
    int c   = tid & 63;     // channel
    for (int i0 = 0; i0 < cnt; i0 += 16) {
        int i = i0 + grp;
        bool act = (i < cnt);
        int l = act ? s_list[i] : 0;
        int y = l >> 6, x = l & 63;
        float pv[9]; float ss = 0.f;
        #pragma unroll
        for (int pp = 0; pp < 9; pp++) {
            int ph = pp / 3, pw = pp % 3;
            int yy = y + ph - 1, xx = x + pw - 1;
            float t = 0.f;
            if (yy >= 0 && yy < Hh && xx >= 0 && xx < Ww)
                t = bgin[(b * NC + c) * Ls + yy * Ww + xx] * (1.f - m[yy * Ww + xx]);
            t += EPSF;
            pv[pp] = t; ss += t * t;
        }
        #pragma unroll
        for (int o = 16; o > 0; o >>= 1) ss += __shfl_xor_sync(0xffffffffu, ss, o);
        if (lane == 0) s_norm[warp] = ss;
        __syncthreads();
        float norm = sqrtf(s_norm[grp * 2] + s_norm[grp * 2 + 1]);
        if (act) {
            #pragma unroll
            for (int pp = 0; pp < 9; pp++)
                g_K[b][i][c * 9 + pp] = pv[pp] / norm;
        }
        __syncthreads();
    }
}

// ---------------------------------------------------------------------------
// K2: corr[i][s] = <K_i, fg patch at s>.  (unchanged from round 5)
// Grid (64 y, 4 cand-quarter, Bz) = 512 blocks.
// ---------------------------------------------------------------------------
__global__ void __launch_bounds__(256) k_corr(const float* __restrict__ fgin) {
    int b = blockIdx.z;
    int cnt = g_cnt[b];
    int y  = blockIdx.x;
    int iq = blockIdx.y;                 // 0..3
    int qq = (cnt + 3) >> 2;
    int ibeg = iq * qq, iend = min(ibeg + qq, cnt);
    if (ibeg >= iend) return;

    int tid = threadIdx.x;
    int cgi = tid >> 4;                  // 0..15 channel-pair group
    int xq  = tid & 15;                  // x quad
    int xbase = xq * 4;

    __shared__ float sfg[32][3][68];     // 25.5KB; col j holds fg x = j-1
    __shared__ float skc[CQ][KD];        // 6.9KB
    __shared__ float buf[16][193];       // 12.1KB

    for (int i0 = ibeg; i0 < iend; i0 += CQ) {
        int nch = min(CQ, iend - i0);
        float acc[CQ][4];
        #pragma unroll
        for (int j = 0; j < CQ; j++)
            #pragma unroll
            for (int xo = 0; xo < 4; xo++) acc[j][xo] = 0.f;

        for (int t = tid; t < nch * (KD / 4); t += 256) {
            int i = t / (KD / 4), k = t % (KD / 4);
            ((float4*)skc[i])[k] = ((const float4*)&g_K[b][i0 + i][0])[k];
        }

        for (int half = 0; half < 2; half++) {
            for (int t = tid; t < 32 * 3 * 68; t += 256) {
                int ch = t / 204, rem = t % 204;
                int r = rem / 68, j = rem % 68;
                int gy = y - 1 + r;
                float v = 0.f;
                if (gy >= 0 && gy < Hh && j >= 1 && j <= 64)
                    v = fgin[(b * NC + half * 32 + ch) * Ls + gy * Ww + (j - 1)];
                sfg[ch][r][j] = v;
            }
            __syncthreads();

            #pragma unroll
            for (int c2 = 0; c2 < 2; c2++) {
                int ch = cgi * 2 + c2;
                int cglob = half * 32 + ch;
                float w[3][6];
                #pragma unroll
                for (int r = 0; r < 3; r++) {
                    float4 a = *(const float4*)&sfg[ch][r][xbase];
                    float2 e = *(const float2*)&sfg[ch][r][xbase + 4];
                    w[r][0] = a.x; w[r][1] = a.y; w[r][2] = a.z; w[r][3] = a.w;
                    w[r][4] = e.x; w[r][5] = e.y;
                }
                for (int j = 0; j < nch; j++) {
                    const float* kk = &skc[j][cglob * 9];
                    float k0 = kk[0], k1 = kk[1], k2 = kk[2];
                    float k3 = kk[3], k4 = kk[4], k5 = kk[5];
                    float k6 = kk[6], k7 = kk[7], k8 = kk[8];
                    #pragma unroll
                    for (int xo = 0; xo < 4; xo++) {
                        acc[j][xo] += k0 * w[0][xo]     + k1 * w[0][xo + 1] + k2 * w[0][xo + 2]
                                    + k3 * w[1][xo]     + k4 * w[1][xo + 1] + k5 * w[1][xo + 2]
                                    + k6 * w[2][xo]     + k7 * w[2][xo + 1] + k8 * w[2][xo + 2];
                    }
                }
            }
            __syncthreads();
        }

        for (int j = 0; j < nch; j++)
            #pragma unroll
            for (int xo = 0; xo < 4; xo++)
                buf[cgi][j * 64 + xbase + xo] = acc[j][xo];
        __syncthreads();
        if (tid < nch * 64) {
            float s = 0.f;
            #pragma unroll
            for (int g = 0; g < 16; g++) s += buf[g][tid];
            int j = tid >> 6, x = tid & 63;
            g_corr[b][i0 + j][y * Ww + x] = s;
        }
        __syncthreads();
    }
}

// ---------------------------------------------------------------------------
// K3 (FUSED softmax + rec + flow): grid (64 y, 4 cg, Bz), 256 threads.
// Threads t<192 are "score role" (r=t/64 in 0..2 -> global row y-1+r, x=t&63):
// they compute v = 10*boxsum(corr) from 5 staged corr rows, per-position
// softmax with closed-form masked-row denominator, write scores to smem.
// All 256 threads then accumulate rec for 16 channels (cg slice) x 4 x each.
// cg==0, r==1 threads also emit flow (argmax, ascending order, strict >).
// Fast path: cnt<=FCH (single chunk). Generic: 3-pass chunked (correct, slow).
// ---------------------------------------------------------------------------
__global__ void __launch_bounds__(256) k_softrec(const float* __restrict__ fgin,
                                                 const float* __restrict__ mask,
                                                 float* __restrict__ att,
                                                 float* __restrict__ flow) {
    int b = blockIdx.z, cg = blockIdx.y, y = blockIdx.x;
    int cnt = g_cnt[b];
    int tid = threadIdx.x;

    __shared__ float corr5[FCH][5][68];  // 21.8KB; col j holds corr x = j-1
    __shared__ float sk[FCH][144];       // 9.2KB  (this cg's 16-channel slice)
    __shared__ float ssc[FCH][3][72];    // 13.8KB; col j holds score x = j-1
    __shared__ float smask[64];
    __shared__ int   sl[FCH];

    if (tid < 64) smask[tid] = mask[b * Ls + y * Ww + tid];
    for (int t = tid; t < FCH * 3 * 72; t += 256) ((float*)ssc)[t] = 0.f;

    // score-role setup
    int sr = tid >> 6;                   // 0..3 (valid role when <3)
    int sx = tid & 63;
    bool isScore = (tid < 192);
    int gyr = y - 1 + sr;
    bool validRow = isScore && (gyr >= 0) && (gyr < Hh);

    // rec-role setup
    int c16 = tid >> 4, xg = tid & 15;
    int c = cg * 16 + c16;
    int xbase = xg * 4;
    float acc[4] = {0.f, 0.f, 0.f, 0.f};

    float vmax = (cnt < Ls) ? 0.f : -INFINITY;
    float bestv = -INFINITY; int bestl = 0;

    if (cnt <= FCH) {
        // ---------------- fast path: single chunk ----------------
        for (int t = tid; t < cnt * 144; t += 256) {
            int i = t / 144, k = t % 144;
            sk[i][k] = g_K[b][i][cg * 144 + k];
        }
        for (int t = tid; t < cnt * 340; t += 256) {
            int i = t / 340, rem = t % 340;
            int rr = rem / 68, j = rem % 68;
            int gy = y - 2 + rr;
            float v = 0.f;
            if (gy >= 0 && gy < Hh && j >= 1 && j <= 64)
                v = g_corr[b][i][gy * Ww + (j - 1)];
            corr5[i][rr][j] = v;
        }
        if (tid < cnt) sl[tid] = g_list[b][tid];
        __syncthreads();

        if (isScore) {
            for (int i = 0; i < cnt; i++) {
                float a = 0.f;
                #pragma unroll
                for (int dy = 0; dy < 3; dy++)
                    #pragma unroll
                    for (int dx = 0; dx < 3; dx++)
                        a += corr5[i][sr + dy][sx + dx];
                float vv = 10.f * a;
                ssc[i][sr][sx + 1] = vv;
                vmax = fmaxf(vmax, vv);
            }
            float denom = (float)(Ls - cnt) * expf(-vmax);
            for (int i = 0; i < cnt; i++) {
                float vv = ssc[i][sr][sx + 1];
                float e = expf(vv - vmax);
                denom += e;
                if (vv > bestv) { bestv = vv; bestl = sl[i]; }  // ascending -> first max
                ssc[i][sr][sx + 1] = validRow ? e : 0.f;
            }
            float inv = 1.f / denom;
            for (int i = 0; i < cnt; i++) ssc[i][sr][sx + 1] *= inv;

            if (cg == 0 && sr == 1) {
                int lb = (cnt > 0) ? bestl : 0;
                flow[(b * 2 + 0) * Ls + y * Ww + sx] = (float)(lb >> 6) - (float)y;
                flow[(b * 2 + 1) * Ls + y * Ww + sx] = (float)(lb & 63) - (float)sx;
            }
        }
        __syncthreads();

        for (int i = 0; i < cnt; i++) {
            float ki[9];
            #pragma unroll
            for (int p = 0; p < 9; p++) ki[p] = sk[i][c16 * 9 + p];
            #pragma unroll
            for (int ph = 0; ph < 3; ph++) {
                const float* row = ssc[i][2 - ph];   // yy = y+1-ph
                float4 a4 = *(const float4*)&row[xbase];
                float2 e2 = *(const float2*)&row[xbase + 4];
                float w0 = a4.x, w1 = a4.y, w2 = a4.z, w3 = a4.w, w4 = e2.x, w5 = e2.y;
                acc[0] += ki[ph * 3 + 0] * w2 + ki[ph * 3 + 1] * w1 + ki[ph * 3 + 2] * w0;
                acc[1] += ki[ph * 3 + 0] * w3 + ki[ph * 3 + 1] * w2 + ki[ph * 3 + 2] * w1;
                acc[2] += ki[ph * 3 + 0] * w4 + ki[ph * 3 + 1] * w3 + ki[ph * 3 + 2] * w2;
                acc[3] += ki[ph * 3 + 0] * w5 + ki[ph * 3 + 1] * w4 + ki[ph * 3 + 2] * w3;
            }
        }
    } else {
        // ------------- generic chunked path (any cnt): 3 passes -------------
        // Pass A: vmax + argmax
        for (int c0 = 0; c0 < cnt; c0 += FCH) {
            int n = min(FCH, cnt - c0);
            for (int t = tid; t < n * 340; t += 256) {
                int i = t / 340, rem = t % 340;
                int rr = rem / 68, j = rem % 68;
                int gy = y - 2 + rr;
                float v = 0.f;
                if (gy >= 0 && gy < Hh && j >= 1 && j <= 64)
                    v = g_corr[b][c0 + i][gy * Ww + (j - 1)];
                corr5[i][rr][j] = v;
            }
            if (tid < n) sl[tid] = g_list[b][c0 + tid];
            __syncthreads();
            if (isScore) {
                for (int i = 0; i < n; i++) {
                    float a = 0.f;
                    #pragma unroll
                    for (int dy = 0; dy < 3; dy++)
                        #pragma unroll
                        for (int dx = 0; dx < 3; dx++)
                            a += corr5[i][sr + dy][sx + dx];
                    float vv = 10.f * a;
                    vmax = fmaxf(vmax, vv);
                    if (sr == 1 && vv > bestv) { bestv = vv; bestl = sl[i]; }
                }
            }
            __syncthreads();
        }
        float denom = (cnt < Ls) ? (float)(Ls - cnt) * expf(-vmax) : 0.f;
        // Pass B: denom
        for (int c0 = 0; c0 < cnt; c0 += FCH) {
            int n = min(FCH, cnt - c0);
            for (int t = tid; t < n * 340; t += 256) {
                int i = t / 340, rem = t % 340;
                int rr = rem / 68, j = rem % 68;
                int gy = y - 2 + rr;
                float v = 0.f;
                if (gy >= 0 && gy < Hh && j >= 1 && j <= 64)
                    v = g_corr[b][c0 + i][gy * Ww + (j - 1)];
                corr5[i][rr][j] = v;
            }
            __syncthreads();
            if (isScore) {
                for (int i = 0; i < n; i++) {
                    float a = 0.f;
                    #pragma unroll
                    for (int dy = 0; dy < 3; dy++)
                        #pragma unroll
                        for (int dx = 0; dx < 3; dx++)
                            a += corr5[i][sr + dy][sx + dx];
                    denom += expf(10.f * a - vmax);
                }
            }
            __syncthreads();
        }
        float inv = 1.f / denom;
        if (cg == 0 && isScore && sr == 1) {
            int lb = (cnt > 0) ? bestl : 0;
            flow[(b * 2 + 0) * Ls + y * Ww + sx] = (float)(lb >> 6) - (float)y;
            flow[(b * 2 + 1) * Ls + y * Ww + sx] = (float)(lb & 63) - (float)sx;
        }
        // Pass C: scores + rec
        for (int c0 = 0; c0 < cnt; c0 += FCH) {
            int n = min(FCH, cnt - c0);
            for (int t = tid; t < n * 340; t += 256) {
                int i = t / 340, rem = t % 340;
                int rr = rem / 68, j = rem % 68;
                int gy = y - 2 + rr;
                float v = 0.f;
                if (gy >= 0 && gy < Hh && j >= 1 && j <= 64)
                    v = g_corr[b][c0 + i][gy * Ww + (j - 1)];
                corr5[i][rr][j] = v;
            }
            for (int t = tid; t < n * 144; t += 256) {
                int i = t / 144, k = t % 144;
                sk[i][k] = g_K[b][c0 + i][cg * 144 + k];
            }
            __syncthreads();
            if (isScore) {
                for (int i = 0; i < n; i++) {
                    float a = 0.f;
                    #pragma unroll
                    for (int dy = 0; dy < 3; dy++)
                        #pragma unroll
                        for (int dx = 0; dx < 3; dx++)
                            a += corr5[i][sr + dy][sx + dx];
                    float e = expf(10.f * a - vmax) * inv;
                    ssc[i][sr][sx + 1] = validRow ? e : 0.f;
                }
            }
            __syncthreads();
            for (int i = 0; i < n; i++) {
                float ki[9];
                #pragma unroll
                for (int p = 0; p < 9; p++) ki[p] = sk[i][c16 * 9 + p];
                #pragma unroll
                for (int ph = 0; ph < 3; ph++) {
                    const float* row = ssc[i][2 - ph];
                    float4 a4 = *(const float4*)&row[xbase];
                    float2 e2 = *(const float2*)&row[xbase + 4];
                    float w0 = a4.x, w1 = a4.y, w2 = a4.z, w3 = a4.w, w4 = e2.x, w5 = e2.y;
                    acc[0] += ki[ph * 3 + 0] * w2 + ki[ph * 3 + 1] * w1 + ki[ph * 3 + 2] * w0;
                    acc[1] += ki[ph * 3 + 0] * w3 + ki[ph * 3 + 1] * w2 + ki[ph * 3 + 2] * w1;
                    acc[2] += ki[ph * 3 + 0] * w4 + ki[ph * 3 + 1] * w3 + ki[ph * 3 + 2] * w2;
                    acc[3] += ki[ph * 3 + 0] * w5 + ki[ph * 3 + 1] * w4 + ki[ph * 3 + 2] * w3;
                }
            }
            __syncthreads();
        }
    }

    // epilogue: final = (rec*m/9)*m + fg*(1-m)
    const float* fgrow = fgin + (b * NC + c) * Ls + y * Ww + xbase;
    float4 fgv = *(const float4*)fgrow;
    float4 o;
    {
        float m0 = smask[xbase + 0], m1 = smask[xbase + 1];
        float m2 = smask[xbase + 2], m3 = smask[xbase + 3];
        o.x = ((acc[0] * m0) / 9.f) * m0 + fgv.x * (1.f - m0);
        o.y = ((acc[1] * m1) / 9.f) * m1 + fgv.y * (1.f - m1);
        o.z = ((acc[2] * m2) / 9.f) * m2 + fgv.z * (1.f - m2);
        o.w = ((acc[3] * m3) / 9.f) * m3 + fgv.w * (1.f - m3);
    }
    *(float4*)(att + (b * NC + c) * Ls + y * Ww + xbase) = o;
}

// ---------------------------------------------------------------------------
extern "C" void kernel_launch(void* const* d_in, const int* in_sizes, int n_in,
                              void* d_out, int out_size) {
    const float* fg   = (const float*)d_in[0];   // foreground [2,64,64,64]
    const float* bg   = (const float*)d_in[1];   // background [2,64,64,64]
    const float* mask = (const float*)d_in[2];   // mask       [2,1,64,64]
    float* att  = (float*)d_out;                 // attended   [2,64,64,64]
    float* flow = (float*)d_out + Bz * NC * Ls;  // flow       [2,2,64,64]

    k_scanbuild<<<Bz, 1024>>>(mask, bg);
    k_corr<<<dim3(64, 4, Bz), 256>>>(fg);
    k_softrec<<<dim3(64, 4, Bz), 256>>>(fg, mask, att, flow);
}

// round 7
// speedup vs baseline: 1.4125x; 1.4125x over previous
#include <cuda_runtime.h>
#include <math.h>

// Problem constants: b=2, nc=64, H=W=64
#define Bz 2
#define NC 64
#define Hh 64
#define Ww 64
#define Ls 4096          // H*W
#define KD 576           // nc * 3 * 3
#define EPSF 1e-7f
#define MAXC 24          // fast-path candidate capacity in k_soft
#define CQ   3           // k_corr candidate chunk per block
#define RCH  12          // k_rec candidate chunk

// Scratch (worst-case cnt == Ls; actual data gives cnt ~ 12 per sample)
__device__ int   g_cnt[Bz];
__device__ int   g_list[Bz][Ls];
__device__ float g_K[Bz][Ls][KD];     // normalized bg patch rows (candidates only)
__device__ float g_corr[Bz][Ls][Ls];  // corr rows   (candidates only)
__device__ float g_sc[Bz][Ls][Ls];    // score rows  (candidates only)

// ---------------------------------------------------------------------------
// K1: per-sample, ONE 1024-thread block: stage mask in smem (4 coalesced LDGs
// per thread), compute mm[l] from smem, single-pass block scan, ordered
// candidate compaction.
// ---------------------------------------------------------------------------
__global__ void k_scan(const float* __restrict__ mask) {
    int b = blockIdx.x;
    int tid = threadIdx.x, lane = tid & 31, warp = tid >> 5;
    __shared__ float sm[Ls];          // 16KB
    __shared__ int   wsum[32];

    #pragma unroll
    for (int j = 0; j < 4; j++)
        sm[tid + j * 1024] = mask[b * Ls + tid + j * 1024];
    __syncthreads();

    int ok[4]; int myc = 0;
    #pragma unroll
    for (int j = 0; j < 4; j++) {
        int l = tid * 4 + j;
        int y = l >> 6, x = l & 63;
        int o = 1;
        #pragma unroll
        for (int dy = -1; dy <= 1; dy++) {
            int yy = y + dy;
            if (yy < 0 || yy >= Hh) continue;
            #pragma unroll
            for (int dx = -1; dx <= 1; dx++) {
                int xx = x + dx;
                if (xx >= 0 && xx < Ww && sm[yy * Ww + xx] != 0.0f) o = 0;
            }
        }
        ok[j] = o; myc += o;
    }
    int v = myc;
    #pragma unroll
    for (int off = 1; off < 32; off <<= 1) {
        int t = __shfl_up_sync(0xffffffffu, v, off);
        if (lane >= off) v += t;
    }
    if (lane == 31) wsum[warp] = v;
    __syncthreads();
    if (warp == 0) {
        int t = wsum[lane];
        #pragma unroll
        for (int off = 1; off < 32; off <<= 1) {
            int u = __shfl_up_sync(0xffffffffu, t, off);
            if (lane >= off) t += u;
        }
        wsum[lane] = t;
    }
    __syncthreads();
    int excl = (v - myc) + (warp > 0 ? wsum[warp - 1] : 0);
    #pragma unroll
    for (int j = 0; j < 4; j++)
        if (ok[j]) g_list[b][excl++] = tid * 4 + j;
    if (tid == 0) g_cnt[b] = wsum[31];
}

// ---------------------------------------------------------------------------
// K2: one block per candidate (stride loop), 576 threads: thread k handles
// kernel element k = c*9+pp. One bg load + one mask load, two-level norm
// reduction, one store.
// ---------------------------------------------------------------------------
__global__ void __launch_bounds__(576) k_build(const float* __restrict__ bgin,
                                               const float* __restrict__ mask) {
    int b = blockIdx.y;
    int cnt = g_cnt[b];
    int tid = threadIdx.x;            // 0..575
    int lane = tid & 31, warp = tid >> 5;   // 18 warps
    int c = tid / 9, pp = tid % 9;
    int ph = pp / 3, pw = pp % 3;
    __shared__ float wred[18];

    for (int i = blockIdx.x; i < cnt; i += gridDim.x) {
        int l = g_list[b][i];
        int y = l >> 6, x = l & 63;
        int yy = y + ph - 1, xx = x + pw - 1;
        float v = 0.f;
        if (yy >= 0 && yy < Hh && xx >= 0 && xx < Ww)
            v = bgin[(b * NC + c) * Ls + yy * Ww + xx]
                * (1.f - mask[b * Ls + yy * Ww + xx]);
        v += EPSF;
        float ss = v * v;
        #pragma unroll
        for (int o = 16; o > 0; o >>= 1) ss += __shfl_xor_sync(0xffffffffu, ss, o);
        if (lane == 0) wred[warp] = ss;
        __syncthreads();
        float tot = 0.f;
        #pragma unroll
        for (int w = 0; w < 18; w++) tot += wred[w];
        g_K[b][i][tid] = v / sqrtf(tot);
        __syncthreads();
    }
}

// ---------------------------------------------------------------------------
// K3: corr[i][s] = <K_i, fg patch at s>.  (proven round-5 version)
// Grid (64 y, 4 cand-quarter, Bz) = 512 blocks.
// ---------------------------------------------------------------------------
__global__ void __launch_bounds__(256) k_corr(const float* __restrict__ fgin) {
    int b = blockIdx.z;
    int cnt = g_cnt[b];
    int y  = blockIdx.x;
    int iq = blockIdx.y;                 // 0..3
    int qq = (cnt + 3) >> 2;
    int ibeg = iq * qq, iend = min(ibeg + qq, cnt);
    if (ibeg >= iend) return;

    int tid = threadIdx.x;
    int cgi = tid >> 4;                  // 0..15 channel-pair group
    int xq  = tid & 15;                  // x quad
    int xbase = xq * 4;

    __shared__ float sfg[32][3][68];     // 25.5KB; col j holds fg x = j-1
    __shared__ float skc[CQ][KD];        // 6.9KB
    __shared__ float buf[16][193];       // 12.1KB

    for (int i0 = ibeg; i0 < iend; i0 += CQ) {
        int nch = min(CQ, iend - i0);
        float acc[CQ][4];
        #pragma unroll
        for (int j = 0; j < CQ; j++)
            #pragma unroll
            for (int xo = 0; xo < 4; xo++) acc[j][xo] = 0.f;

        for (int t = tid; t < nch * (KD / 4); t += 256) {
            int i = t / (KD / 4), k = t % (KD / 4);
            ((float4*)skc[i])[k] = ((const float4*)&g_K[b][i0 + i][0])[k];
        }

        for (int half = 0; half < 2; half++) {
            for (int t = tid; t < 32 * 3 * 68; t += 256) {
                int ch = t / 204, rem = t % 204;
                int r = rem / 68, j = rem % 68;
                int gy = y - 1 + r;
                float v = 0.f;
                if (gy >= 0 && gy < Hh && j >= 1 && j <= 64)
                    v = fgin[(b * NC + half * 32 + ch) * Ls + gy * Ww + (j - 1)];
                sfg[ch][r][j] = v;
            }
            __syncthreads();

            #pragma unroll
            for (int c2 = 0; c2 < 2; c2++) {
                int ch = cgi * 2 + c2;
                int cglob = half * 32 + ch;
                float w[3][6];
                #pragma unroll
                for (int r = 0; r < 3; r++) {
                    float4 a = *(const float4*)&sfg[ch][r][xbase];
                    float2 e = *(const float2*)&sfg[ch][r][xbase + 4];
                    w[r][0] = a.x; w[r][1] = a.y; w[r][2] = a.z; w[r][3] = a.w;
                    w[r][4] = e.x; w[r][5] = e.y;
                }
                for (int j = 0; j < nch; j++) {
                    const float* kk = &skc[j][cglob * 9];
                    float k0 = kk[0], k1 = kk[1], k2 = kk[2];
                    float k3 = kk[3], k4 = kk[4], k5 = kk[5];
                    float k6 = kk[6], k7 = kk[7], k8 = kk[8];
                    #pragma unroll
                    for (int xo = 0; xo < 4; xo++) {
                        acc[j][xo] += k0 * w[0][xo]     + k1 * w[0][xo + 1] + k2 * w[0][xo + 2]
                                    + k3 * w[1][xo]     + k4 * w[1][xo + 1] + k5 * w[1][xo + 2]
                                    + k6 * w[2][xo]     + k7 * w[2][xo + 1] + k8 * w[2][xo + 2];
                    }
                }
            }
            __syncthreads();
        }

        for (int j = 0; j < nch; j++)
            #pragma unroll
            for (int xo = 0; xo < 4; xo++)
                buf[cgi][j * 64 + xbase + xo] = acc[j][xo];
        __syncthreads();
        if (tid < nch * 64) {
            float s = 0.f;
            #pragma unroll
            for (int g = 0; g < 16; g++) s += buf[g][tid];
            int j = tid >> 6, x = tid & 63;
            g_corr[b][i0 + j][y * Ww + x] = s;
        }
        __syncthreads();
    }
}

// 3x3 spatial box-sum of a global corr row (zero outside grid) — slow path
__device__ __forceinline__ float boxsum_g(const float* __restrict__ row, int y, int x) {
    float a = 0.f;
    #pragma unroll
    for (int dy = -1; dy <= 1; dy++) {
        int yy = y + dy;
        if (yy < 0 || yy >= Hh) continue;
        const float* r = row + yy * Ww;
        #pragma unroll
        for (int dx = -1; dx <= 1; dx++) {
            int xx = x + dx;
            if (xx >= 0 && xx < Ww) a += r[xx];
        }
    }
    return a;
}

// ---------------------------------------------------------------------------
// K4: softmax/argmax/flow (proven round-5 version). Grid (32, Bz), 128 thr.
// ---------------------------------------------------------------------------
__global__ void k_soft(float* __restrict__ flowout) {
    int b = blockIdx.y;
    int cnt = g_cnt[b];
    int tid = threadIdx.x;               // 0..127
    int r0 = blockIdx.x * 2;
    int q = tid >> 6, x = tid & 63;
    int y = r0 + q;
    int s = y * Ww + x;

    __shared__ float raw[MAXC][4][64];   // 24KB
    __shared__ float esm[MAXC][128];     // 12KB
    __shared__ int   sl[MAXC];

    if (cnt <= MAXC) {
        for (int i = 0; i < cnt; i++) {
            #pragma unroll
            for (int t2 = 0; t2 < 2; t2++) {
                int t = tid + t2 * 128;
                int j = t >> 6, xx = t & 63;
                int gr = r0 - 1 + j;
                raw[i][j][xx] = (gr >= 0 && gr < Hh) ? g_corr[b][i][gr * Ww + xx] : 0.f;
            }
        }
        if (tid < cnt) sl[tid] = g_list[b][tid];
        __syncthreads();

        float vmax = (cnt < Ls) ? 0.f : -INFINITY;
        for (int i = 0; i < cnt; i++) {
            float a = 0.f;
            #pragma unroll
            for (int dy = 0; dy < 3; dy++) {
                #pragma unroll
                for (int dx = -1; dx <= 1; dx++) {
                    int xx = x + dx;
                    if (xx >= 0 && xx < 64) a += raw[i][q + dy][xx];
                }
            }
            float vv = 10.f * a;
            esm[i][tid] = vv;
            vmax = fmaxf(vmax, vv);
        }
        float denom = (cnt < Ls) ? (float)(Ls - cnt) * expf(-vmax) : 0.f;
        float bestv = -INFINITY; int bestl = 0;
        for (int i = 0; i < cnt; i++) {
            float vv = esm[i][tid];
            float e = expf(vv - vmax);
            denom += e;
            if (vv > bestv) { bestv = vv; bestl = sl[i]; }   // ascending -> first max
            esm[i][tid] = e;
        }
        float inv = 1.f / denom;
        for (int i = 0; i < cnt; i++)
            g_sc[b][i][s] = esm[i][tid] * inv;

        flowout[(b * 2 + 0) * Ls + s] = (float)(bestl >> 6) - (float)y;
        flowout[(b * 2 + 1) * Ls + s] = (float)(bestl & 63) - (float)x;
    } else {
        float vmax = (cnt < Ls) ? 0.f : -INFINITY;
        for (int i = 0; i < cnt; i++) {
            float vv = 10.f * boxsum_g(&g_corr[b][i][0], y, x);
            vmax = fmaxf(vmax, vv);
            g_sc[b][i][s] = vv;
        }
        float denom = (cnt < Ls) ? (float)(Ls - cnt) * expf(-vmax) : 0.f;
        float bestv = -INFINITY; int bestl = 0;
        for (int i = 0; i < cnt; i++) {
            float vv = g_sc[b][i][s];
            float e = expf(vv - vmax);
            denom += e;
            if (vv > bestv) { bestv = vv; bestl = g_list[b][i]; }
            g_sc[b][i][s] = e;
        }
        float inv = 1.f / denom;
        for (int i = 0; i < cnt; i++) g_sc[b][i][s] *= inv;
        flowout[(b * 2 + 0) * Ls + s] = (float)(bestl >> 6) - (float)y;
        flowout[(b * 2 + 1) * Ls + s] = (float)(bestl & 63) - (float)x;
    }
}

// ---------------------------------------------------------------------------
// K5: rec (proven round-5 version). Grid (64 y, 4 cg, Bz) = 512 blocks.
// ---------------------------------------------------------------------------
__global__ void __launch_bounds__(256) k_rec(const float* __restrict__ fgin,
                                             const float* __restrict__ mask,
                                             float* __restrict__ att) {
    int b = blockIdx.z, cg = blockIdx.y, y = blockIdx.x;
    int cnt = g_cnt[b];
    int tid = threadIdx.x;
    int c16 = tid >> 4, xg = tid & 15;
    int c = cg * 16 + c16;
    int xbase = xg * 4;

    __shared__ float sk[RCH][16 * 9];    // 6.9KB  (this cg's channel slice)
    __shared__ float ssc[RCH][3][72];    // 10.1KB; col j holds score x = j-1
    __shared__ float smask[64];

    if (tid < 64) smask[tid] = mask[b * Ls + y * Ww + tid];

    float acc[4] = {0.f, 0.f, 0.f, 0.f};

    for (int c0 = 0; c0 < cnt; c0 += RCH) {
        int nchunk = min(RCH, cnt - c0);
        for (int t = tid; t < nchunk * 144; t += 256) {
            int i = t / 144, k = t % 144;
            sk[i][k] = g_K[b][c0 + i][cg * 144 + k];
        }
        for (int t = tid; t < nchunk * 216; t += 256) {
            int i = t / 216, rem = t % 216;
            int r = rem / 72, j = rem % 72;
            int gy = y - 1 + r;
            float v = 0.f;
            if (gy >= 0 && gy < Hh && j >= 1 && j <= 64)
                v = g_sc[b][c0 + i][gy * Ww + (j - 1)];
            ssc[i][r][j] = v;
        }
        __syncthreads();

        for (int i = 0; i < nchunk; i++) {
            float ki[9];
            #pragma unroll
            for (int p = 0; p < 9; p++) ki[p] = sk[i][c16 * 9 + p];
            #pragma unroll
            for (int ph = 0; ph < 3; ph++) {
                const float* row = ssc[i][2 - ph];   // yy = y+1-ph
                float4 a = *(const float4*)&row[xbase];
                float2 e = *(const float2*)&row[xbase + 4];
                float w0 = a.x, w1 = a.y, w2 = a.z, w3 = a.w, w4 = e.x, w5 = e.y;
                acc[0] += ki[ph * 3 + 0] * w2 + ki[ph * 3 + 1] * w1 + ki[ph * 3 + 2] * w0;
                acc[1] += ki[ph * 3 + 0] * w3 + ki[ph * 3 + 1] * w2 + ki[ph * 3 + 2] * w1;
                acc[2] += ki[ph * 3 + 0] * w4 + ki[ph * 3 + 1] * w3 + ki[ph * 3 + 2] * w2;
                acc[3] += ki[ph * 3 + 0] * w5 + ki[ph * 3 + 1] * w4 + ki[ph * 3 + 2] * w3;
            }
        }
        __syncthreads();
    }

    const float* fgrow = fgin + (b * NC + c) * Ls + y * Ww + xbase;
    float4 fgv = *(const float4*)fgrow;
    float4 o;
    {
        float m0 = smask[xbase + 0], m1 = smask[xbase + 1];
        float m2 = smask[xbase + 2], m3 = smask[xbase + 3];
        o.x = ((acc[0] * m0) / 9.f) * m0 + fgv.x * (1.f - m0);
        o.y = ((acc[1] * m1) / 9.f) * m1 + fgv.y * (1.f - m1);
        o.z = ((acc[2] * m2) / 9.f) * m2 + fgv.z * (1.f - m2);
        o.w = ((acc[3] * m3) / 9.f) * m3 + fgv.w * (1.f - m3);
    }
    *(float4*)(att + (b * NC + c) * Ls + y * Ww + xbase) = o;
}

// ---------------------------------------------------------------------------
extern "C" void kernel_launch(void* const* d_in, const int* in_sizes, int n_in,
                              void* d_out, int out_size) {
    const float* fg   = (const float*)d_in[0];   // foreground [2,64,64,64]
    const float* bg   = (const float*)d_in[1];   // background [2,64,64,64]
    const float* mask = (const float*)d_in[2];   // mask       [2,1,64,64]
    float* att  = (float*)d_out;                 // attended   [2,64,64,64]
    float* flow = (float*)d_out + Bz * NC * Ls;  // flow       [2,2,64,64]

    k_scan<<<Bz, 1024>>>(mask);
    k_build<<<dim3(64, Bz), 576>>>(bg, mask);
    k_corr<<<dim3(64, 4, Bz), 256>>>(fg);
    k_soft<<<dim3(32, Bz), 128>>>(flow);
    k_rec<<<dim3(64, 4, Bz), 256>>>(fg, mask, att);
}

// round 8
// speedup vs baseline: 1.4394x; 1.0191x over previous
#include <cuda_runtime.h>
#include <math.h>

// Problem constants: b=2, nc=64, H=W=64
#define Bz 2
#define NC 64
#define Hh 64
#define Ww 64
#define Ls 4096          // H*W
#define KD 576           // nc * 3 * 3
#define EPSF 1e-7f
#define MAXC 24          // fast-path candidate capacity in k_soft
#define CQ   3           // k_corr candidate chunk per block
#define RCH  12          // k_rec candidate chunk

// Scratch (worst-case cnt == Ls; actual data gives cnt ~ 12 per sample)
__device__ int   g_cnt[Bz];
__device__ int   g_list[Bz][Ls];
__device__ float g_K[Bz][Ls][KD];     // normalized bg patch rows (candidates only)
__device__ float g_corr[Bz][Ls][Ls];  // corr rows   (candidates only)
__device__ float g_sc[Bz][Ls][Ls];    // score rows  (candidates only)

// ---------------------------------------------------------------------------
// K1: per-sample, ONE 1024-thread block: stage mask in smem (4 coalesced LDGs
// per thread), compute mm[l] from smem, single-pass block scan, ordered
// candidate compaction.
// ---------------------------------------------------------------------------
__global__ void k_scan(const float* __restrict__ mask) {
    int b = blockIdx.x;
    int tid = threadIdx.x, lane = tid & 31, warp = tid >> 5;
    __shared__ float sm[Ls];          // 16KB
    __shared__ int   wsum[32];

    #pragma unroll
    for (int j = 0; j < 4; j++)
        sm[tid + j * 1024] = mask[b * Ls + tid + j * 1024];
    __syncthreads();

    int ok[4]; int myc = 0;
    #pragma unroll
    for (int j = 0; j < 4; j++) {
        int l = tid * 4 + j;
        int y = l >> 6, x = l & 63;
        int o = 1;
        #pragma unroll
        for (int dy = -1; dy <= 1; dy++) {
            int yy = y + dy;
            if (yy < 0 || yy >= Hh) continue;
            #pragma unroll
            for (int dx = -1; dx <= 1; dx++) {
                int xx = x + dx;
                if (xx >= 0 && xx < Ww && sm[yy * Ww + xx] != 0.0f) o = 0;
            }
        }
        ok[j] = o; myc += o;
    }
    int v = myc;
    #pragma unroll
    for (int off = 1; off < 32; off <<= 1) {
        int t = __shfl_up_sync(0xffffffffu, v, off);
        if (lane >= off) v += t;
    }
    if (lane == 31) wsum[warp] = v;
    __syncthreads();
    if (warp == 0) {
        int t = wsum[lane];
        #pragma unroll
        for (int off = 1; off < 32; off <<= 1) {
            int u = __shfl_up_sync(0xffffffffu, t, off);
            if (lane >= off) t += u;
        }
        wsum[lane] = t;
    }
    __syncthreads();
    int excl = (v - myc) + (warp > 0 ? wsum[warp - 1] : 0);
    #pragma unroll
    for (int j = 0; j < 4; j++)
        if (ok[j]) g_list[b][excl++] = tid * 4 + j;
    if (tid == 0) g_cnt[b] = wsum[31];
}

// ---------------------------------------------------------------------------
// K2: one block per candidate (stride loop), 576 threads: thread k handles
// kernel element k = c*9+pp. One bg load + one mask load, two-level norm
// reduction, one store.
// ---------------------------------------------------------------------------
__global__ void __launch_bounds__(576) k_build(const float* __restrict__ bgin,
                                               const float* __restrict__ mask) {
    int b = blockIdx.y;
    int cnt = g_cnt[b];
    int tid = threadIdx.x;            // 0..575
    int lane = tid & 31, warp = tid >> 5;   // 18 warps
    int c = tid / 9, pp = tid % 9;
    int ph = pp / 3, pw = pp % 3;
    __shared__ float wred[18];

    for (int i = blockIdx.x; i < cnt; i += gridDim.x) {
        int l = g_list[b][i];
        int y = l >> 6, x = l & 63;
        int yy = y + ph - 1, xx = x + pw - 1;
        float v = 0.f;
        if (yy >= 0 && yy < Hh && xx >= 0 && xx < Ww)
            v = bgin[(b * NC + c) * Ls + yy * Ww + xx]
                * (1.f - mask[b * Ls + yy * Ww + xx]);
        v += EPSF;
        float ss = v * v;
        #pragma unroll
        for (int o = 16; o > 0; o >>= 1) ss += __shfl_xor_sync(0xffffffffu, ss, o);
        if (lane == 0) wred[warp] = ss;
        __syncthreads();
        float tot = 0.f;
        #pragma unroll
        for (int w = 0; w < 18; w++) tot += wred[w];
        g_K[b][i][tid] = v / sqrtf(tot);
        __syncthreads();
    }
}

// ---------------------------------------------------------------------------
// K3: corr[i][s] = <K_i, fg patch at s>.  (proven round-5 version)
// Grid (64 y, 4 cand-quarter, Bz) = 512 blocks.
// ---------------------------------------------------------------------------
__global__ void __launch_bounds__(256) k_corr(const float* __restrict__ fgin) {
    int b = blockIdx.z;
    int cnt = g_cnt[b];
    int y  = blockIdx.x;
    int iq = blockIdx.y;                 // 0..3
    int qq = (cnt + 3) >> 2;
    int ibeg = iq * qq, iend = min(ibeg + qq, cnt);
    if (ibeg >= iend) return;

    int tid = threadIdx.x;
    int cgi = tid >> 4;                  // 0..15 channel-pair group
    int xq  = tid & 15;                  // x quad
    int xbase = xq * 4;

    __shared__ float sfg[32][3][68];     // 25.5KB; col j holds fg x = j-1
    __shared__ float skc[CQ][KD];        // 6.9KB
    __shared__ float buf[16][193];       // 12.1KB

    for (int i0 = ibeg; i0 < iend; i0 += CQ) {
        int nch = min(CQ, iend - i0);
        float acc[CQ][4];
        #pragma unroll
        for (int j = 0; j < CQ; j++)
            #pragma unroll
            for (int xo = 0; xo < 4; xo++) acc[j][xo] = 0.f;

        for (int t = tid; t < nch * (KD / 4); t += 256) {
            int i = t / (KD / 4), k = t % (KD / 4);
            ((float4*)skc[i])[k] = ((const float4*)&g_K[b][i0 + i][0])[k];
        }

        for (int half = 0; half < 2; half++) {
            for (int t = tid; t < 32 * 3 * 68; t += 256) {
                int ch = t / 204, rem = t % 204;
                int r = rem / 68, j = rem % 68;
                int gy = y - 1 + r;
                float v = 0.f;
                if (gy >= 0 && gy < Hh && j >= 1 && j <= 64)
                    v = fgin[(b * NC + half * 32 + ch) * Ls + gy * Ww + (j - 1)];
                sfg[ch][r][j] = v;
            }
            __syncthreads();

            #pragma unroll
            for (int c2 = 0; c2 < 2; c2++) {
                int ch = cgi * 2 + c2;
                int cglob = half * 32 + ch;
                float w[3][6];
                #pragma unroll
                for (int r = 0; r < 3; r++) {
                    float4 a = *(const float4*)&sfg[ch][r][xbase];
                    float2 e = *(const float2*)&sfg[ch][r][xbase + 4];
                    w[r][0] = a.x; w[r][1] = a.y; w[r][2] = a.z; w[r][3] = a.w;
                    w[r][4] = e.x; w[r][5] = e.y;
                }
                for (int j = 0; j < nch; j++) {
                    const float* kk = &skc[j][cglob * 9];
                    float k0 = kk[0], k1 = kk[1], k2 = kk[2];
                    float k3 = kk[3], k4 = kk[4], k5 = kk[5];
                    float k6 = kk[6], k7 = kk[7], k8 = kk[8];
                    #pragma unroll
                    for (int xo = 0; xo < 4; xo++) {
                        acc[j][xo] += k0 * w[0][xo]     + k1 * w[0][xo + 1] + k2 * w[0][xo + 2]
                                    + k3 * w[1][xo]     + k4 * w[1][xo + 1] + k5 * w[1][xo + 2]
                                    + k6 * w[2][xo]     + k7 * w[2][xo + 1] + k8 * w[2][xo + 2];
                    }
                }
            }
            __syncthreads();
        }

        for (int j = 0; j < nch; j++)
            #pragma unroll
            for (int xo = 0; xo < 4; xo++)
                buf[cgi][j * 64 + xbase + xo] = acc[j][xo];
        __syncthreads();
        if (tid < nch * 64) {
            float s = 0.f;
            #pragma unroll
            for (int g = 0; g < 16; g++) s += buf[g][tid];
            int j = tid >> 6, x = tid & 63;
            g_corr[b][i0 + j][y * Ww + x] = s;
        }
        __syncthreads();
    }
}

// 3x3 spatial box-sum of a global corr row (zero outside grid) — slow path
__device__ __forceinline__ float boxsum_g(const float* __restrict__ row, int y, int x) {
    float a = 0.f;
    #pragma unroll
    for (int dy = -1; dy <= 1; dy++) {
        int yy = y + dy;
        if (yy < 0 || yy >= Hh) continue;
        const float* r = row + yy * Ww;
        #pragma unroll
        for (int dx = -1; dx <= 1; dx++) {
            int xx = x + dx;
            if (xx >= 0 && xx < Ww) a += r[xx];
        }
    }
    return a;
}

// ---------------------------------------------------------------------------
// K4: softmax/argmax/flow v2. Grid (64 y, Bz) = 128 blocks, 256 threads =
// 4 candidate-groups x 64 x. Groups split candidate load+boxsum 4-way;
// combine (vmax/denom/argmax, ascending i) is redundant per thread from smem;
// score writes group-split. Fallback for cnt>MAXC preserved (group 0).
// ---------------------------------------------------------------------------
__global__ void __launch_bounds__(256) k_soft(float* __restrict__ flowout) {
    int b = blockIdx.y, y = blockIdx.x;
    int cnt = g_cnt[b];
    int tid = threadIdx.x;               // 0..255
    int g = tid >> 6, x = tid & 63;
    int s = y * Ww + x;

    __shared__ float raw[MAXC][3][64];   // 18KB rows y-1..y+1 per candidate
    __shared__ float vsh[MAXC][64];      // 6KB
    __shared__ int   sl[MAXC];

    if (cnt <= MAXC) {
        // group-split load: candidate i handled by group i%4
        for (int i = g; i < cnt; i += 4) {
            #pragma unroll
            for (int r = 0; r < 3; r++) {
                int gy = y - 1 + r;
                raw[i][r][x] = (gy >= 0 && gy < Hh) ? g_corr[b][i][gy * Ww + x] : 0.f;
            }
        }
        if (tid < cnt) sl[tid] = g_list[b][tid];
        __syncthreads();

        // group-split boxsum
        for (int i = g; i < cnt; i += 4) {
            float a = 0.f;
            #pragma unroll
            for (int r = 0; r < 3; r++) {
                #pragma unroll
                for (int dx = -1; dx <= 1; dx++) {
                    int xx = x + dx;
                    if (xx >= 0 && xx < 64) a += raw[i][r][xx];
                }
            }
            vsh[i][x] = 10.f * a;
        }
        __syncthreads();

        // redundant per-thread combine (ascending i: exact prior order)
        float vmax = (cnt < Ls) ? 0.f : -INFINITY;
        for (int i = 0; i < cnt; i++) vmax = fmaxf(vmax, vsh[i][x]);
        float denom = (cnt < Ls) ? (float)(Ls - cnt) * expf(-vmax) : 0.f;
        float bestv = -INFINITY; int bestl = 0;
        for (int i = 0; i < cnt; i++) {
            float vv = vsh[i][x];
            denom += expf(vv - vmax);
            if (vv > bestv) { bestv = vv; bestl = sl[i]; }   // first max
        }
        float inv = 1.f / denom;

        // group-split score writes
        for (int i = g; i < cnt; i += 4)
            g_sc[b][i][s] = expf(vsh[i][x] - vmax) * inv;

        if (g == 0) {
            flowout[(b * 2 + 0) * Ls + s] = (float)(bestl >> 6) - (float)y;
            flowout[(b * 2 + 1) * Ls + s] = (float)(bestl & 63) - (float)x;
        }
    } else if (g == 0) {
        // generic correct fallback (64 threads do full per-s work)
        float vmax = (cnt < Ls) ? 0.f : -INFINITY;
        for (int i = 0; i < cnt; i++) {
            float vv = 10.f * boxsum_g(&g_corr[b][i][0], y, x);
            vmax = fmaxf(vmax, vv);
            g_sc[b][i][s] = vv;
        }
        float denom = (cnt < Ls) ? (float)(Ls - cnt) * expf(-vmax) : 0.f;
        float bestv = -INFINITY; int bestl = 0;
        for (int i = 0; i < cnt; i++) {
            float vv = g_sc[b][i][s];
            float e = expf(vv - vmax);
            denom += e;
            if (vv > bestv) { bestv = vv; bestl = g_list[b][i]; }
            g_sc[b][i][s] = e;
        }
        float inv = 1.f / denom;
        for (int i = 0; i < cnt; i++) g_sc[b][i][s] *= inv;
        flowout[(b * 2 + 0) * Ls + s] = (float)(bestl >> 6) - (float)y;
        flowout[(b * 2 + 1) * Ls + s] = (float)(bestl & 63) - (float)x;
    }
}

// ---------------------------------------------------------------------------
// K5: rec (proven round-5 version). Grid (64 y, 4 cg, Bz) = 512 blocks.
// ---------------------------------------------------------------------------
__global__ void __launch_bounds__(256) k_rec(const float* __restrict__ fgin,
                                             const float* __restrict__ mask,
                                             float* __restrict__ att) {
    int b = blockIdx.z, cg = blockIdx.y, y = blockIdx.x;
    int cnt = g_cnt[b];
    int tid = threadIdx.x;
    int c16 = tid >> 4, xg = tid & 15;
    int c = cg * 16 + c16;
    int xbase = xg * 4;

    __shared__ float sk[RCH][16 * 9];    // 6.9KB  (this cg's channel slice)
    __shared__ float ssc[RCH][3][72];    // 10.1KB; col j holds score x = j-1
    __shared__ float smask[64];

    if (tid < 64) smask[tid] = mask[b * Ls + y * Ww + tid];

    float acc[4] = {0.f, 0.f, 0.f, 0.f};

    for (int c0 = 0; c0 < cnt; c0 += RCH) {
        int nchunk = min(RCH, cnt - c0);
        for (int t = tid; t < nchunk * 144; t += 256) {
            int i = t / 144, k = t % 144;
            sk[i][k] = g_K[b][c0 + i][cg * 144 + k];
        }
        for (int t = tid; t < nchunk * 216; t += 256) {
            int i = t / 216, rem = t % 216;
            int r = rem / 72, j = rem % 72;
            int gy = y - 1 + r;
            float v = 0.f;
            if (gy >= 0 && gy < Hh && j >= 1 && j <= 64)
                v = g_sc[b][c0 + i][gy * Ww + (j - 1)];
            ssc[i][r][j] = v;
        }
        __syncthreads();

        for (int i = 0; i < nchunk; i++) {
            float ki[9];
            #pragma unroll
            for (int p = 0; p < 9; p++) ki[p] = sk[i][c16 * 9 + p];
            #pragma unroll
            for (int ph = 0; ph < 3; ph++) {
                const float* row = ssc[i][2 - ph];   // yy = y+1-ph
                float4 a = *(const float4*)&row[xbase];
                float2 e = *(const float2*)&row[xbase + 4];
                float w0 = a.x, w1 = a.y, w2 = a.z, w3 = a.w, w4 = e.x, w5 = e.y;
                acc[0] += ki[ph * 3 + 0] * w2 + ki[ph * 3 + 1] * w1 + ki[ph * 3 + 2] * w0;
                acc[1] += ki[ph * 3 + 0] * w3 + ki[ph * 3 + 1] * w2 + ki[ph * 3 + 2] * w1;
                acc[2] += ki[ph * 3 + 0] * w4 + ki[ph * 3 + 1] * w3 + ki[ph * 3 + 2] * w2;
                acc[3] += ki[ph * 3 + 0] * w5 + ki[ph * 3 + 1] * w4 + ki[ph * 3 + 2] * w3;
            }
        }
        __syncthreads();
    }

    const float* fgrow = fgin + (b * NC + c) * Ls + y * Ww + xbase;
    float4 fgv = *(const float4*)fgrow;
    float4 o;
    {
        float m0 = smask[xbase + 0], m1 = smask[xbase + 1];
        float m2 = smask[xbase + 2], m3 = smask[xbase + 3];
        o.x = ((acc[0] * m0) / 9.f) * m0 + fgv.x * (1.f - m0);
        o.y = ((acc[1] * m1) / 9.f) * m1 + fgv.y * (1.f - m1);
        o.z = ((acc[2] * m2) / 9.f) * m2 + fgv.z * (1.f - m2);
        o.w = ((acc[3] * m3) / 9.f) * m3 + fgv.w * (1.f - m3);
    }
    *(float4*)(att + (b * NC + c) * Ls + y * Ww + xbase) = o;
}

// ---------------------------------------------------------------------------
extern "C" void kernel_launch(void* const* d_in, const int* in_sizes, int n_in,
                              void* d_out, int out_size) {
    const float* fg   = (const float*)d_in[0];   // foreground [2,64,64,64]
    const float* bg   = (const float*)d_in[1];   // background [2,64,64,64]
    const float* mask = (const float*)d_in[2];   // mask       [2,1,64,64]
    float* att  = (float*)d_out;                 // attended   [2,64,64,64]
    float* flow = (float*)d_out + Bz * NC * Ls;  // flow       [2,2,64,64]

    k_scan<<<Bz, 1024>>>(mask);
    k_build<<<dim3(64, Bz), 576>>>(bg, mask);
    k_corr<<<dim3(64, 4, Bz), 256>>>(fg);
    k_soft<<<dim3(64, Bz), 256>>>(flow);
    k_rec<<<dim3(64, 4, Bz), 256>>>(fg, mask, att);
}